// round 10
// baseline (speedup 1.0000x reference)
#include <cuda_runtime.h>
#include <cstdint>

// Problem constants
constexpr int AN = 10;     // agents
constexpr int BN = 32;     // batch
constexpr int FSN = 2;     // static features
constexpr int FDN = 8;     // dynamic features
constexpr int HN = 512;    // hidden
constexpr int SN = 512;    // stations
constexpr int H3 = 3 * HN; // 1536
constexpr int H2 = 2 * HN; // 1024

// ---------------- scratch (no allocations allowed) ----------------
__device__ float g_attp[AN * HN * 12];   // {ms0,ms1,md0..7,va,0} per (a,h)
__device__ float g_ptrp[AN * HN * 4];    // {ps0,ps1,pconst,vp} per (a,h)
__device__ float g_Pc[AN * HN * 2];      // Wp_c @ Ws
__device__ float g_aconst[AN * HN];      // Wa_s@bs + Wa_d@bd
__device__ float g_G[AN * H3 * 2];       // Wih @ Wdec  (rank-2 GRU input)
__device__ float g_gib[AN * H3];         // Wih @ bdec + bih
__device__ float g_gh[AN * H3 * BN];     // Whh @ last_hh^T + bhh, [a][j3][b]
__device__ float g_hnew[AN * BN * HN];   // new hidden, [a][b][h]
__device__ float g_c[AN * HN * BN];      // Wa_h@h_new + aconst, [a][h][b]
__device__ float g_l[AN * BN * SN];      // partial attention logits, h in [0,256)
__device__ float g_l2[AN * BN * SN];     // partial attention logits, h in [256,512)
__device__ float g_d[AN * BN * HN];      // pointer per-h additive term, [ab][h]

// ---------------- packed f32x2 helpers ----------------
#define FFMA2(d, a, b, c) \
    asm("fma.rn.f32x2 %0, %1, %2, %3;" : "=l"(d) : "l"(a), "l"(b), "l"(c))
#define ADDX2(d, a, b) \
    asm("add.rn.f32x2 %0, %1, %2;" : "=l"(d) : "l"(a), "l"(b))

__device__ __forceinline__ unsigned long long pack2(float lo, float hi) {
    unsigned long long r;
    asm("mov.b64 %0, {%1, %2};" : "=l"(r) : "f"(lo), "f"(hi));
    return r;
}
__device__ __forceinline__ void unpack2(unsigned long long v, float& lo, float& hi) {
    asm("mov.b64 {%0, %1}, %2;" : "=f"(lo), "=f"(hi) : "l"(v));
}

// ---------------- math helpers ----------------
// accurate tanh (~1e-7 abs): 2 MUFU + ~4 FMA-pipe ops, branch-free.
__device__ __forceinline__ float tanh_acc(float x) {
    float e = __expf(2.0f * x);
    return 1.0f - __fdividef(2.0f, e + 1.0f);
}
// fast tanh: 1 MUFU (MUFU.TANH). Used only pre-softmax (error damped;
// measured total rel_err 1.04e-6 with this in the attention path).
__device__ __forceinline__ float tanh_fast(float x) {
    float y;
    asm("tanh.approx.f32 %0, %1;" : "=f"(y) : "f"(x));
    return y;
}
__device__ __forceinline__ float rcp_fast(float x) {
    float y;
    asm("rcp.approx.f32 %0, %1;" : "=f"(y) : "f"(x));
    return y;
}
__device__ __forceinline__ float sigmoid_acc(float x) {
    return __fdividef(1.0f, 1.0f + __expf(-x));
}

// =====================================================================
// K12: fused K1 (low-rank precompute, HBM-bound) + K2 (Whh GEMM,
// FMA-bound). Independent work; one launch so the two bottlenecks
// overlap on different pipes instead of serializing.
// =====================================================================
constexpr int K2_BLOCKS = 240;   // A * (H3/64)
constexpr int K1_BLOCKS = 2560;  // (A*H + A*3H) warps / 8

__global__ void __launch_bounds__(256) k12_pre_gh(
    const float* __restrict__ Wa, const float* __restrict__ Wp,
    const float* __restrict__ Ws, const float* __restrict__ Wd,
    const float* __restrict__ bs, const float* __restrict__ bd,
    const float* __restrict__ va, const float* __restrict__ vp,
    const float* __restrict__ Wih, const float* __restrict__ Wdec,
    const float* __restrict__ bdec, const float* __restrict__ bih,
    const float* __restrict__ Whh, const float* __restrict__ bhh,
    const float* __restrict__ lhh)
{
    __shared__ float sh[BN * 258];          // used by the K2 path only
    int lane = threadIdx.x & 31;

    if (blockIdx.x < K2_BLOCKS) {
        // ---------------- K2 body: gh = Whh @ last_hh^T + bhh ----------------
        int a = blockIdx.x / 24;
        int jblk = (blockIdx.x % 24) * 64;
        int wid = threadIdx.x >> 5;
        int j3b = jblk + wid * 8;

        unsigned long long acc2[8];
        #pragma unroll
        for (int j = 0; j < 8; j++) acc2[j] = 0ull;

        for (int kc = 0; kc < 2; kc++) {
            if (kc) __syncthreads();
            for (int i = threadIdx.x; i < BN * 256; i += 256) {
                int b = i >> 8, k = i & 255;
                sh[b * 258 + k] = lhh[b * HN + kc * 256 + k];
            }
            __syncthreads();
            const float* w0 = Whh + (size_t)(a * H3 + j3b) * HN + kc * 256;
            #pragma unroll 2
            for (int k4 = 0; k4 < 256; k4 += 4) {
                unsigned long long h2a =
                    *reinterpret_cast<const unsigned long long*>(&sh[lane * 258 + k4]);
                unsigned long long h2b =
                    *reinterpret_cast<const unsigned long long*>(&sh[lane * 258 + k4 + 2]);
                #pragma unroll
                for (int j = 0; j < 8; j++) {
                    ulonglong2 wv = *reinterpret_cast<const ulonglong2*>(w0 + (size_t)j * HN + k4);
                    FFMA2(acc2[j], wv.x, h2a, acc2[j]);
                    FFMA2(acc2[j], wv.y, h2b, acc2[j]);
                }
            }
        }
        #pragma unroll
        for (int j = 0; j < 8; j++) {
            float lo, hi; unpack2(acc2[j], lo, hi);
            g_gh[((size_t)a * H3 + j3b + j) * BN + lane] = lo + hi + bhh[a * H3 + j3b + j];
        }
        return;
    }

    // ---------------- K1 body: one warp per output row ----------------
    int wg = ((blockIdx.x - K2_BLOCKS) * blockDim.x + threadIdx.x) >> 5;

    if (wg < AN * HN) {
        int a = wg / HN, h = wg % HN;
        const float* war = Wa + (size_t)(a * HN + h) * H3;
        const float* wpr = Wp + (size_t)(a * HN + h) * H2;
        float acc[16];
        #pragma unroll
        for (int i = 0; i < 16; i++) acc[i] = 0.0f;

        for (int j = lane; j < HN; j += 32) {
            float was = war[j];
            float wad = war[HN + j];
            float wps = wpr[j];
            float wpc = wpr[HN + j];
            float ws0 = Ws[j * 2 + 0], ws1 = Ws[j * 2 + 1];
            acc[0] = fmaf(was, ws0, acc[0]);
            acc[1] = fmaf(was, ws1, acc[1]);
            const float* wdj = Wd + (size_t)(a * HN + j) * FDN;
            #pragma unroll
            for (int f = 0; f < 8; f++) acc[2 + f] = fmaf(wad, wdj[f], acc[2 + f]);
            acc[10] = fmaf(was, bs[j], fmaf(wad, bd[a * HN + j], acc[10]));
            acc[11] = fmaf(wps, ws0, acc[11]);
            acc[12] = fmaf(wps, ws1, acc[12]);
            acc[13] = fmaf(wpc, ws0, acc[13]);
            acc[14] = fmaf(wpc, ws1, acc[14]);
            acc[15] = fmaf(wps + wpc, bs[j], acc[15]);
        }
        #pragma unroll
        for (int i = 0; i < 16; i++) {
            #pragma unroll
            for (int off = 16; off > 0; off >>= 1)
                acc[i] += __shfl_down_sync(0xffffffffu, acc[i], off);
        }
        if (lane == 0) {
            float* ap = g_attp + (size_t)(a * HN + h) * 12;
            ap[0] = acc[0]; ap[1] = acc[1];
            #pragma unroll
            for (int f = 0; f < 8; f++) ap[2 + f] = acc[2 + f];
            ap[10] = va[a * HN + h];
            ap[11] = 0.0f;
            g_aconst[a * HN + h] = acc[10];
            float* pp = g_ptrp + (size_t)(a * HN + h) * 4;
            pp[0] = acc[11]; pp[1] = acc[12]; pp[2] = acc[15]; pp[3] = vp[a * HN + h];
            g_Pc[(a * HN + h) * 2 + 0] = acc[13];
            g_Pc[(a * HN + h) * 2 + 1] = acc[14];
        }
    } else if (wg < AN * HN + AN * H3) {
        int idx = wg - AN * HN;
        int a = idx / H3, j3 = idx % H3;
        const float* wr = Wih + (size_t)(a * H3 + j3) * HN;
        float g0 = 0.0f, g1 = 0.0f, gb = 0.0f;
        for (int k = lane; k < HN; k += 32) {
            float w = wr[k];
            g0 = fmaf(w, Wdec[(a * HN + k) * 2 + 0], g0);
            g1 = fmaf(w, Wdec[(a * HN + k) * 2 + 1], g1);
            gb = fmaf(w, bdec[a * HN + k], gb);
        }
        #pragma unroll
        for (int off = 16; off > 0; off >>= 1) {
            g0 += __shfl_down_sync(0xffffffffu, g0, off);
            g1 += __shfl_down_sync(0xffffffffu, g1, off);
            gb += __shfl_down_sync(0xffffffffu, gb, off);
        }
        if (lane == 0) {
            g_G[(size_t)(a * H3 + j3) * 2 + 0] = g0;
            g_G[(size_t)(a * H3 + j3) * 2 + 1] = g1;
            g_gib[a * H3 + j3] = gb + bih[a * H3 + j3];
        }
    }
}

// =====================================================================
// K3: GRU elementwise (gi collapsed to rank-2), write h_new (+ hh output)
// =====================================================================
__global__ void __launch_bounds__(256) k3_gru(
    const float* __restrict__ dec, const float* __restrict__ lhh,
    float* __restrict__ out_hh, int write_out)
{
    int idx = blockIdx.x * blockDim.x + threadIdx.x;
    int h = idx % HN;
    int b = (idx / HN) % BN;
    int a = idx / (BN * HN);

    float d0 = dec[b * 2 + 0], d1 = dec[b * 2 + 1];

    int jr = h, jz = HN + h, jn = 2 * HN + h;
    const float* Gb = g_G + (size_t)a * H3 * 2;
    const float* gib = g_gib + (size_t)a * H3;
    float ir = fmaf(Gb[jr * 2], d0, fmaf(Gb[jr * 2 + 1], d1, gib[jr]));
    float iz = fmaf(Gb[jz * 2], d0, fmaf(Gb[jz * 2 + 1], d1, gib[jz]));
    float in_ = fmaf(Gb[jn * 2], d0, fmaf(Gb[jn * 2 + 1], d1, gib[jn]));

    const float* ghb = g_gh + (size_t)a * H3 * BN;
    float hr = ghb[(size_t)jr * BN + b];
    float hz = ghb[(size_t)jz * BN + b];
    float hn = ghb[(size_t)jn * BN + b];

    float r = sigmoid_acc(ir + hr);
    float z = sigmoid_acc(iz + hz);
    float n = tanh_acc(in_ + r * hn);
    float hprev = lhh[b * HN + h];
    float hnew = fmaf(1.0f - z, n, z * hprev);

    g_hnew[((size_t)a * BN + b) * HN + h] = hnew;
    if (write_out) out_hh[((size_t)a * BN + b) * HN + h] = hnew;
}

// =====================================================================
// K4: c[a][h][b] = sum_j Wa[a][h][2H+j] * h_new[a][b][j] + aconst[a][h]
// Packed-k structure; 2 rows/warp, 16 rows/block. Grid = 320.
// =====================================================================
__global__ void __launch_bounds__(256) k4_c(const float* __restrict__ Wa)
{
    __shared__ float sh[BN * 258];
    int a = blockIdx.x / 32;
    int hblk = (blockIdx.x % 32) * 16;
    int wid = threadIdx.x >> 5, lane = threadIdx.x & 31;
    int hb = hblk + wid * 2;

    unsigned long long acc2[2];
    #pragma unroll
    for (int j = 0; j < 2; j++) acc2[j] = 0ull;

    for (int kc = 0; kc < 2; kc++) {
        if (kc) __syncthreads();
        for (int i = threadIdx.x; i < BN * 256; i += 256) {
            int b = i >> 8, k = i & 255;
            sh[b * 258 + k] = g_hnew[((size_t)a * BN + b) * HN + kc * 256 + k];
        }
        __syncthreads();
        const float* w0 = Wa + (size_t)(a * HN + hb) * H3 + 2 * HN + kc * 256;
        #pragma unroll 2
        for (int k4 = 0; k4 < 256; k4 += 4) {
            unsigned long long h2a =
                *reinterpret_cast<const unsigned long long*>(&sh[lane * 258 + k4]);
            unsigned long long h2b =
                *reinterpret_cast<const unsigned long long*>(&sh[lane * 258 + k4 + 2]);
            #pragma unroll
            for (int j = 0; j < 2; j++) {
                ulonglong2 wv = *reinterpret_cast<const ulonglong2*>(w0 + (size_t)j * H3 + k4);
                FFMA2(acc2[j], wv.x, h2a, acc2[j]);
                FFMA2(acc2[j], wv.y, h2b, acc2[j]);
            }
        }
    }
    #pragma unroll
    for (int j = 0; j < 2; j++) {
        float lo, hi; unpack2(acc2[j], lo, hi);
        g_c[((size_t)a * HN + hb + j) * BN + lane] = lo + hi + g_aconst[a * HN + hb + j];
    }
}

// =====================================================================
// K5a: partial attention logits, 4 stations/thread, 64-thread blocks.
// R9 ncu: occ=20.4%, issue=41%, fma=43%, L1=44.8% -> latency-bound at
// low warp count (grid 640 = 4.32 blocks/SM avg). Regrid: each block
// covers a station-half (64 thr x 4 stations = 256), grid = A*B*2*2 =
// 1280, launch_bounds(64,9): 9 blocks/SM by smem (216KB), 8.65 avg ->
// ~17 warps/SM (+33%) and 1.04x tail. Math/layout unchanged.
// =====================================================================
__global__ void __launch_bounds__(64, 9) k5a_attn(
    const float* __restrict__ st, const float* __restrict__ dyn)
{
    constexpr int HH = HN / 2;                      // 256 h per block
    int ab = blockIdx.x >> 2;
    int shalf = (blockIdx.x >> 1) & 1, hhalf = blockIdx.x & 1;
    int a = ab >> 5, b = ab & 31;
    __shared__ __align__(16) float sB[HH * 24];     // 24KB: 12 splat-pairs per h
    int t = threadIdx.x;

    // staging: flat index -> coalesced LDG + conflict-free STS.64
    float2* s2 = reinterpret_cast<float2*>(sB);
    const float* arow = g_attp + ((size_t)a * HN + hhalf * HH) * 12;
    int hbase = hhalf * HH;
    for (int idx = t; idx < HH * 12; idx += 64) {
        int hl = idx / 12, k = idx - hl * 12;
        float v = (k == 11) ? g_c[((size_t)a * HN + hbase + hl) * BN + b] : arow[idx];
        s2[idx] = make_float2(v, v);
    }

    // 4 stations per thread within the station-half
    int s0 = shalf * 256 + t, s1 = s0 + 64, s2i = s0 + 128, s3 = s0 + 192;
    unsigned long long uA[10], uB[10];
    const float* stb = st + (size_t)b * FSN * SN;
    uA[0] = pack2(stb[s0], stb[s1]);           uB[0] = pack2(stb[s2i], stb[s3]);
    uA[1] = pack2(stb[SN + s0], stb[SN + s1]); uB[1] = pack2(stb[SN + s2i], stb[SN + s3]);
    const float* dyb = dyn + (size_t)(a * BN + b) * FDN * SN;
    #pragma unroll
    for (int f = 0; f < 8; f++) {
        uA[2 + f] = pack2(dyb[f * SN + s0], dyb[f * SN + s1]);
        uB[2 + f] = pack2(dyb[f * SN + s2i], dyb[f * SN + s3]);
    }
    __syncthreads();

    unsigned long long laccA = 0, laccB = 0;
    #pragma unroll 2
    for (int h = 0; h < HH; h++) {
        const ulonglong2* row = reinterpret_cast<const ulonglong2*>(sB + h * 24);
        ulonglong2 q0 = row[0], q1 = row[1], q2 = row[2];
        ulonglong2 q3 = row[3], q4 = row[4], q5 = row[5];
        unsigned long long caA = q5.y, cbA = 0ull;   // 4 independent chains
        unsigned long long caB = q5.y, cbB = 0ull;
        FFMA2(caA, q0.x, uA[0], caA); FFMA2(cbA, q0.y, uA[1], cbA);
        FFMA2(caB, q0.x, uB[0], caB); FFMA2(cbB, q0.y, uB[1], cbB);
        FFMA2(caA, q1.x, uA[2], caA); FFMA2(cbA, q1.y, uA[3], cbA);
        FFMA2(caB, q1.x, uB[2], caB); FFMA2(cbB, q1.y, uB[3], cbB);
        FFMA2(caA, q2.x, uA[4], caA); FFMA2(cbA, q2.y, uA[5], cbA);
        FFMA2(caB, q2.x, uB[4], caB); FFMA2(cbB, q2.y, uB[5], cbB);
        FFMA2(caA, q3.x, uA[6], caA); FFMA2(cbA, q3.y, uA[7], cbA);
        FFMA2(caB, q3.x, uB[6], caB); FFMA2(cbB, q3.y, uB[7], cbB);
        FFMA2(caA, q4.x, uA[8], caA); FFMA2(cbA, q4.y, uA[9], cbA);
        FFMA2(caB, q4.x, uB[8], caB); FFMA2(cbB, q4.y, uB[9], cbB);
        unsigned long long accA, accB;
        ADDX2(accA, caA, cbA);
        ADDX2(accB, caB, cbB);
        float a0, a1, a2, a3;
        unpack2(accA, a0, a1);
        unpack2(accB, a2, a3);
        unsigned long long tpA = pack2(tanh_fast(a0), tanh_fast(a1));
        unsigned long long tpB = pack2(tanh_fast(a2), tanh_fast(a3));
        FFMA2(laccA, q5.x, tpA, laccA);             // va pair
        FFMA2(laccB, q5.x, tpB, laccB);
    }
    float l0, l1, l2, l3;
    unpack2(laccA, l0, l1);
    unpack2(laccB, l2, l3);
    float* dst = (hhalf == 0) ? g_l : g_l2;
    dst[(size_t)ab * SN + s0]  = l0;
    dst[(size_t)ab * SN + s1]  = l1;
    dst[(size_t)ab * SN + s2i] = l2;
    dst[(size_t)ab * SN + s3]  = l3;
}

// =====================================================================
// K5b: combine partial logits, softmax over 512, st_w,
// d[h] = Pc.st_w + pconst. Grid = A*B (320), 256 threads. Light.
// =====================================================================
__global__ void __launch_bounds__(256) k5b_soft(const float* __restrict__ st)
{
    int ab = blockIdx.x;
    int a = ab >> 5, b = ab & 31;
    __shared__ float red[256];
    int t = threadIdx.x;

    float l0 = g_l[(size_t)ab * SN + t]       + g_l2[(size_t)ab * SN + t];
    float l1 = g_l[(size_t)ab * SN + t + 256] + g_l2[(size_t)ab * SN + t + 256];

    red[t] = fmaxf(l0, l1);
    __syncthreads();
    #pragma unroll
    for (int o = 128; o > 0; o >>= 1) {
        if (t < o) red[t] = fmaxf(red[t], red[t + o]);
        __syncthreads();
    }
    float m = red[0];
    __syncthreads();

    float e0 = __expf(l0 - m), e1 = __expf(l1 - m);
    red[t] = e0 + e1;
    __syncthreads();
    #pragma unroll
    for (int o = 128; o > 0; o >>= 1) {
        if (t < o) red[t] += red[t + o];
        __syncthreads();
    }
    float inv = __fdividef(1.0f, red[0]);
    __syncthreads();
    float at0 = e0 * inv, at1 = e1 * inv;

    const float* stb = st + (size_t)b * FSN * SN;
    float u00 = stb[t], u10 = stb[t + 256];
    float u01 = stb[SN + t], u11 = stb[SN + t + 256];

    red[t] = fmaf(at0, u00, at1 * u10);
    __syncthreads();
    #pragma unroll
    for (int o = 128; o > 0; o >>= 1) {
        if (t < o) red[t] += red[t + o];
        __syncthreads();
    }
    float stw0 = red[0];
    __syncthreads();

    red[t] = fmaf(at0, u01, at1 * u11);
    __syncthreads();
    #pragma unroll
    for (int o = 128; o > 0; o >>= 1) {
        if (t < o) red[t] += red[t + o];
        __syncthreads();
    }
    float stw1 = red[0];

    for (int h = t; h < HN; h += 256) {
        float pc0 = g_Pc[(a * HN + h) * 2 + 0];
        float pc1 = g_Pc[(a * HN + h) * 2 + 1];
        float pcn = g_ptrp[(size_t)(a * HN + h) * 4 + 2];
        g_d[(size_t)ab * HN + h] = fmaf(pc0, stw0, fmaf(pc1, stw1, pcn));
    }
}

// =====================================================================
// K5c: pointer probs. Grid = A*B*4 (1280) x 64 threads, station-quarter
// per block, packed pair per thread. MUFU-bound; shared-reciprocal
// tanh batch: per h-pair the 4 tanhs use 4 EX2 + ONE RCP (product of
// clamped denominators, each recovered by muls) = 5 MUFU vs 8. Inputs
// clamped to +-9 (tanh(9)=1 in fp32; product <= 1.9e31, no overflow).
// Accuracy: few-ulp absolute -> ~1e-7 on output. tanh.approx for the
// output stays gated (est. ~7.5e-4 rel_err, too close to 1e-3 gate).
// =====================================================================
__global__ void __launch_bounds__(64) k5c_ptr(
    const float* __restrict__ st, float* __restrict__ out_probs)
{
    int ab = blockIdx.x >> 2, q = blockIdx.x & 3;
    int a = ab >> 5, b = ab & 31;
    __shared__ __align__(16) float sP[HN * 8];    // 16KB: 4 splat-pairs per h
    int t = threadIdx.x;

    float2* s2 = reinterpret_cast<float2*>(sP);
    const float* prow = g_ptrp + (size_t)a * HN * 4;
    for (int idx = t; idx < HN * 4; idx += 64) {
        int h = idx >> 2, k = idx & 3;
        float v = (k == 2) ? g_d[(size_t)ab * HN + h] : prow[idx];
        s2[idx] = make_float2(v, v);
    }

    int s0 = q * 128 + t, s1 = s0 + 64;
    const float* stb = st + (size_t)b * FSN * SN;
    unsigned long long up0 = pack2(stb[s0], stb[s1]);
    unsigned long long up1 = pack2(stb[SN + s0], stb[SN + s1]);
    __syncthreads();

    unsigned long long pacc0 = 0, pacc1 = 0;
    #pragma unroll 2
    for (int h = 0; h < HN; h += 2) {
        const ulonglong2* rowX = reinterpret_cast<const ulonglong2*>(sP + h * 8);
        ulonglong2 x0 = rowX[0], x1 = rowX[1];   // {ps0,ps1}, {d,vp}
        const ulonglong2* rowY = reinterpret_cast<const ulonglong2*>(sP + (h + 1) * 8);
        ulonglong2 y0 = rowY[0], y1 = rowY[1];

        unsigned long long accX = x1.x, accY = y1.x;
        FFMA2(accX, x0.x, up0, accX);
        FFMA2(accY, y0.x, up0, accY);
        FFMA2(accX, x0.y, up1, accX);
        FFMA2(accY, y0.y, up1, accY);

        float a0, a1, a2, a3;
        unpack2(accX, a0, a1);
        unpack2(accY, a2, a3);
        // clamp to +-9: tanh saturates to 1.0f within fp32; bounds product
        a0 = fminf(fmaxf(a0, -9.0f), 9.0f);
        a1 = fminf(fmaxf(a1, -9.0f), 9.0f);
        a2 = fminf(fmaxf(a2, -9.0f), 9.0f);
        a3 = fminf(fmaxf(a3, -9.0f), 9.0f);
        // 4 tanhs, one reciprocal: tanh(x) = 1 - 2/(exp(2x)+1)
        float d0 = __expf(2.0f * a0) + 1.0f;
        float d1 = __expf(2.0f * a1) + 1.0f;
        float d2 = __expf(2.0f * a2) + 1.0f;
        float d3 = __expf(2.0f * a3) + 1.0f;
        float p01 = d0 * d1, p23 = d2 * d3;
        float inv = rcp_fast(p01 * p23);
        float inv01 = inv * p23, inv23 = inv * p01;
        float t0 = fmaf(-2.0f, inv01 * d1, 1.0f);
        float t1 = fmaf(-2.0f, inv01 * d0, 1.0f);
        float t2 = fmaf(-2.0f, inv23 * d3, 1.0f);
        float t3 = fmaf(-2.0f, inv23 * d2, 1.0f);

        unsigned long long tpX = pack2(t0, t1);
        unsigned long long tpY = pack2(t2, t3);
        FFMA2(pacc0, x1.y, tpX, pacc0);
        FFMA2(pacc1, y1.y, tpY, pacc1);
    }
    unsigned long long pacc; ADDX2(pacc, pacc0, pacc1);
    float p0, p1; unpack2(pacc, p0, p1);
    out_probs[(size_t)ab * SN + s0] = p0;
    out_probs[(size_t)ab * SN + s1] = p1;
}

// =====================================================================
extern "C" void kernel_launch(void* const* d_in, const int* in_sizes, int n_in,
                              void* d_out, int out_size)
{
    const float* st   = (const float*)d_in[0];   // [B,FS,S]
    const float* dyn  = (const float*)d_in[1];   // [A,B,FD,S]
    const float* dec  = (const float*)d_in[2];   // [B,FS,1]
    const float* lhh  = (const float*)d_in[3];   // [B,H]
    const float* Ws   = (const float*)d_in[4];   // [H,FS]
    const float* bs   = (const float*)d_in[5];   // [H]
    const float* Wd   = (const float*)d_in[6];   // [A,H,FD]
    const float* bd   = (const float*)d_in[7];   // [A,H]
    const float* Wdec = (const float*)d_in[8];   // [A,H,FS]
    const float* bdec = (const float*)d_in[9];   // [A,H]
    const float* Wih  = (const float*)d_in[10];  // [A,3H,H]
    const float* Whh  = (const float*)d_in[11];  // [A,3H,H]
    const float* bih  = (const float*)d_in[12];  // [A,3H]
    const float* bhh  = (const float*)d_in[13];  // [A,3H]
    const float* va   = (const float*)d_in[14];  // [A,H]
    const float* Wa   = (const float*)d_in[15];  // [A,H,3H]
    const float* vp   = (const float*)d_in[16];  // [A,H]
    const float* Wp   = (const float*)d_in[17];  // [A,H,2H]

    float* out = (float*)d_out;
    float* out_probs = out;                         // [A,B,S]
    int have_hh = (out_size >= AN * BN * SN + AN * BN * HN);
    float* out_hh = out + (size_t)AN * BN * SN;     // [A,B,H]

    k12_pre_gh<<<K2_BLOCKS + K1_BLOCKS, 256>>>(
        Wa, Wp, Ws, Wd, bs, bd, va, vp, Wih, Wdec, bdec, bih, Whh, bhh, lhh);
    k3_gru<<<AN * BN * HN / 256, 256>>>(dec, lhh, out_hh, have_hh);
    k4_c<<<320, 256>>>(Wa);
    k5a_attn<<<AN * BN * 4, 64>>>(st, dyn);
    k5b_soft<<<AN * BN, 256>>>(st);
    k5c_ptr<<<AN * BN * 4, 64>>>(st, out_probs);
}

// round 16
// speedup vs baseline: 1.0808x; 1.0808x over previous
#include <cuda_runtime.h>
#include <cstdint>

// Problem constants
constexpr int AN = 10;     // agents
constexpr int BN = 32;     // batch
constexpr int FSN = 2;     // static features
constexpr int FDN = 8;     // dynamic features
constexpr int HN = 512;    // hidden
constexpr int SN = 512;    // stations
constexpr int H3 = 3 * HN; // 1536
constexpr int H2 = 2 * HN; // 1024

// ---------------- scratch (no allocations allowed) ----------------
__device__ float g_attp[AN * HN * 12];   // {ms0,ms1,md0..7,va,0} per (a,h)
__device__ float g_ptrp[AN * HN * 4];    // {ps0,ps1,pconst,vp} per (a,h)
__device__ float g_Pc[AN * HN * 2];      // Wp_c @ Ws
__device__ float g_aconst[AN * HN];      // Wa_s@bs + Wa_d@bd
__device__ float g_G[AN * H3 * 2];       // Wih @ Wdec  (rank-2 GRU input)
__device__ float g_gib[AN * H3];         // Wih @ bdec + bih
__device__ float g_gh[AN * H3 * BN];     // Whh @ last_hh^T + bhh, [a][j3][b]
__device__ float g_hnew[AN * BN * HN];   // new hidden, [a][b][h]
__device__ float g_c[AN * HN * BN];      // Wa_h@h_new + aconst, [a][h][b]
__device__ float g_lp[4 * AN * BN * SN]; // partial attention logits, 4 h-quarters
__device__ float g_d[AN * BN * HN];      // pointer per-h additive term, [ab][h]
__device__ float g_pp[2 * AN * BN * SN]; // partial pointer probs, 2 h-halves

// ---------------- packed f32x2 helpers ----------------
#define FFMA2(d, a, b, c) \
    asm("fma.rn.f32x2 %0, %1, %2, %3;" : "=l"(d) : "l"(a), "l"(b), "l"(c))
#define ADDX2(d, a, b) \
    asm("add.rn.f32x2 %0, %1, %2;" : "=l"(d) : "l"(a), "l"(b))

__device__ __forceinline__ unsigned long long pack2(float lo, float hi) {
    unsigned long long r;
    asm("mov.b64 %0, {%1, %2};" : "=l"(r) : "f"(lo), "f"(hi));
    return r;
}
__device__ __forceinline__ void unpack2(unsigned long long v, float& lo, float& hi) {
    asm("mov.b64 {%0, %1}, %2;" : "=f"(lo), "=f"(hi) : "l"(v));
}

// ---------------- math helpers ----------------
// accurate tanh (~1e-7 abs): 2 MUFU + ~4 FMA-pipe ops, branch-free.
__device__ __forceinline__ float tanh_acc(float x) {
    float e = __expf(2.0f * x);
    return 1.0f - __fdividef(2.0f, e + 1.0f);
}
// fast tanh: 1 MUFU (MUFU.TANH). Used only pre-softmax (error damped;
// measured total rel_err ~1e-6 with this in the attention path).
__device__ __forceinline__ float tanh_fast(float x) {
    float y;
    asm("tanh.approx.f32 %0, %1;" : "=f"(y) : "f"(x));
    return y;
}
__device__ __forceinline__ float sigmoid_acc(float x) {
    return __fdividef(1.0f, 1.0f + __expf(-x));
}

// =====================================================================
// K12: fused K1 (low-rank precompute, HBM-bound) + K2 (Whh GEMM,
// FMA-bound). Independent work; one launch so the two bottlenecks
// overlap on different pipes instead of serializing.
// =====================================================================
constexpr int K2_BLOCKS = 240;   // A * (H3/64)
constexpr int K1_BLOCKS = 2560;  // (A*H + A*3H) warps / 8

__global__ void __launch_bounds__(256) k12_pre_gh(
    const float* __restrict__ Wa, const float* __restrict__ Wp,
    const float* __restrict__ Ws, const float* __restrict__ Wd,
    const float* __restrict__ bs, const float* __restrict__ bd,
    const float* __restrict__ va, const float* __restrict__ vp,
    const float* __restrict__ Wih, const float* __restrict__ Wdec,
    const float* __restrict__ bdec, const float* __restrict__ bih,
    const float* __restrict__ Whh, const float* __restrict__ bhh,
    const float* __restrict__ lhh)
{
    __shared__ float sh[BN * 258];          // used by the K2 path only
    int lane = threadIdx.x & 31;

    if (blockIdx.x < K2_BLOCKS) {
        // ---------------- K2 body: gh = Whh @ last_hh^T + bhh ----------------
        int a = blockIdx.x / 24;
        int jblk = (blockIdx.x % 24) * 64;
        int wid = threadIdx.x >> 5;
        int j3b = jblk + wid * 8;

        unsigned long long acc2[8];
        #pragma unroll
        for (int j = 0; j < 8; j++) acc2[j] = 0ull;

        for (int kc = 0; kc < 2; kc++) {
            if (kc) __syncthreads();
            for (int i = threadIdx.x; i < BN * 256; i += 256) {
                int b = i >> 8, k = i & 255;
                sh[b * 258 + k] = lhh[b * HN + kc * 256 + k];
            }
            __syncthreads();
            const float* w0 = Whh + (size_t)(a * H3 + j3b) * HN + kc * 256;
            #pragma unroll 2
            for (int k4 = 0; k4 < 256; k4 += 4) {
                unsigned long long h2a =
                    *reinterpret_cast<const unsigned long long*>(&sh[lane * 258 + k4]);
                unsigned long long h2b =
                    *reinterpret_cast<const unsigned long long*>(&sh[lane * 258 + k4 + 2]);
                #pragma unroll
                for (int j = 0; j < 8; j++) {
                    ulonglong2 wv = *reinterpret_cast<const ulonglong2*>(w0 + (size_t)j * HN + k4);
                    FFMA2(acc2[j], wv.x, h2a, acc2[j]);
                    FFMA2(acc2[j], wv.y, h2b, acc2[j]);
                }
            }
        }
        #pragma unroll
        for (int j = 0; j < 8; j++) {
            float lo, hi; unpack2(acc2[j], lo, hi);
            g_gh[((size_t)a * H3 + j3b + j) * BN + lane] = lo + hi + bhh[a * H3 + j3b + j];
        }
        return;
    }

    // ---------------- K1 body: one warp per output row ----------------
    int wg = ((blockIdx.x - K2_BLOCKS) * blockDim.x + threadIdx.x) >> 5;

    if (wg < AN * HN) {
        int a = wg / HN, h = wg % HN;
        const float* war = Wa + (size_t)(a * HN + h) * H3;
        const float* wpr = Wp + (size_t)(a * HN + h) * H2;
        float acc[16];
        #pragma unroll
        for (int i = 0; i < 16; i++) acc[i] = 0.0f;

        for (int j = lane; j < HN; j += 32) {
            float was = war[j];
            float wad = war[HN + j];
            float wps = wpr[j];
            float wpc = wpr[HN + j];
            float ws0 = Ws[j * 2 + 0], ws1 = Ws[j * 2 + 1];
            acc[0] = fmaf(was, ws0, acc[0]);
            acc[1] = fmaf(was, ws1, acc[1]);
            const float* wdj = Wd + (size_t)(a * HN + j) * FDN;
            #pragma unroll
            for (int f = 0; f < 8; f++) acc[2 + f] = fmaf(wad, wdj[f], acc[2 + f]);
            acc[10] = fmaf(was, bs[j], fmaf(wad, bd[a * HN + j], acc[10]));
            acc[11] = fmaf(wps, ws0, acc[11]);
            acc[12] = fmaf(wps, ws1, acc[12]);
            acc[13] = fmaf(wpc, ws0, acc[13]);
            acc[14] = fmaf(wpc, ws1, acc[14]);
            acc[15] = fmaf(wps + wpc, bs[j], acc[15]);
        }
        #pragma unroll
        for (int i = 0; i < 16; i++) {
            #pragma unroll
            for (int off = 16; off > 0; off >>= 1)
                acc[i] += __shfl_down_sync(0xffffffffu, acc[i], off);
        }
        if (lane == 0) {
            float* ap = g_attp + (size_t)(a * HN + h) * 12;
            ap[0] = acc[0]; ap[1] = acc[1];
            #pragma unroll
            for (int f = 0; f < 8; f++) ap[2 + f] = acc[2 + f];
            ap[10] = va[a * HN + h];
            ap[11] = 0.0f;
            g_aconst[a * HN + h] = acc[10];
            float* pp = g_ptrp + (size_t)(a * HN + h) * 4;
            pp[0] = acc[11]; pp[1] = acc[12]; pp[2] = acc[15]; pp[3] = vp[a * HN + h];
            g_Pc[(a * HN + h) * 2 + 0] = acc[13];
            g_Pc[(a * HN + h) * 2 + 1] = acc[14];
        }
    } else if (wg < AN * HN + AN * H3) {
        int idx = wg - AN * HN;
        int a = idx / H3, j3 = idx % H3;
        const float* wr = Wih + (size_t)(a * H3 + j3) * HN;
        float g0 = 0.0f, g1 = 0.0f, gb = 0.0f;
        for (int k = lane; k < HN; k += 32) {
            float w = wr[k];
            g0 = fmaf(w, Wdec[(a * HN + k) * 2 + 0], g0);
            g1 = fmaf(w, Wdec[(a * HN + k) * 2 + 1], g1);
            gb = fmaf(w, bdec[a * HN + k], gb);
        }
        #pragma unroll
        for (int off = 16; off > 0; off >>= 1) {
            g0 += __shfl_down_sync(0xffffffffu, g0, off);
            g1 += __shfl_down_sync(0xffffffffu, g1, off);
            gb += __shfl_down_sync(0xffffffffu, gb, off);
        }
        if (lane == 0) {
            g_G[(size_t)(a * H3 + j3) * 2 + 0] = g0;
            g_G[(size_t)(a * H3 + j3) * 2 + 1] = g1;
            g_gib[a * H3 + j3] = gb + bih[a * H3 + j3];
        }
    }
}

// =====================================================================
// K3: GRU elementwise (gi collapsed to rank-2), write h_new (+ hh output)
// =====================================================================
__global__ void __launch_bounds__(256) k3_gru(
    const float* __restrict__ dec, const float* __restrict__ lhh,
    float* __restrict__ out_hh, int write_out)
{
    int idx = blockIdx.x * blockDim.x + threadIdx.x;
    int h = idx % HN;
    int b = (idx / HN) % BN;
    int a = idx / (BN * HN);

    float d0 = dec[b * 2 + 0], d1 = dec[b * 2 + 1];

    int jr = h, jz = HN + h, jn = 2 * HN + h;
    const float* Gb = g_G + (size_t)a * H3 * 2;
    const float* gib = g_gib + (size_t)a * H3;
    float ir = fmaf(Gb[jr * 2], d0, fmaf(Gb[jr * 2 + 1], d1, gib[jr]));
    float iz = fmaf(Gb[jz * 2], d0, fmaf(Gb[jz * 2 + 1], d1, gib[jz]));
    float in_ = fmaf(Gb[jn * 2], d0, fmaf(Gb[jn * 2 + 1], d1, gib[jn]));

    const float* ghb = g_gh + (size_t)a * H3 * BN;
    float hr = ghb[(size_t)jr * BN + b];
    float hz = ghb[(size_t)jz * BN + b];
    float hn = ghb[(size_t)jn * BN + b];

    float r = sigmoid_acc(ir + hr);
    float z = sigmoid_acc(iz + hz);
    float n = tanh_acc(in_ + r * hn);
    float hprev = lhh[b * HN + h];
    float hnew = fmaf(1.0f - z, n, z * hprev);

    g_hnew[((size_t)a * BN + b) * HN + h] = hnew;
    if (write_out) out_hh[((size_t)a * BN + b) * HN + h] = hnew;
}

// =====================================================================
// K4: c[a][h][b] = sum_j Wa[a][h][2H+j] * h_new[a][b][j] + aconst[a][h]
// Packed-k structure; 2 rows/warp, 16 rows/block. Grid = 320.
// =====================================================================
__global__ void __launch_bounds__(256) k4_c(const float* __restrict__ Wa)
{
    __shared__ float sh[BN * 258];
    int a = blockIdx.x / 32;
    int hblk = (blockIdx.x % 32) * 16;
    int wid = threadIdx.x >> 5, lane = threadIdx.x & 31;
    int hb = hblk + wid * 2;

    unsigned long long acc2[2];
    #pragma unroll
    for (int j = 0; j < 2; j++) acc2[j] = 0ull;

    for (int kc = 0; kc < 2; kc++) {
        if (kc) __syncthreads();
        for (int i = threadIdx.x; i < BN * 256; i += 256) {
            int b = i >> 8, k = i & 255;
            sh[b * 258 + k] = g_hnew[((size_t)a * BN + b) * HN + kc * 256 + k];
        }
        __syncthreads();
        const float* w0 = Wa + (size_t)(a * HN + hb) * H3 + 2 * HN + kc * 256;
        #pragma unroll 2
        for (int k4 = 0; k4 < 256; k4 += 4) {
            unsigned long long h2a =
                *reinterpret_cast<const unsigned long long*>(&sh[lane * 258 + k4]);
            unsigned long long h2b =
                *reinterpret_cast<const unsigned long long*>(&sh[lane * 258 + k4 + 2]);
            #pragma unroll
            for (int j = 0; j < 2; j++) {
                ulonglong2 wv = *reinterpret_cast<const ulonglong2*>(w0 + (size_t)j * H3 + k4);
                FFMA2(acc2[j], wv.x, h2a, acc2[j]);
                FFMA2(acc2[j], wv.y, h2b, acc2[j]);
            }
        }
    }
    #pragma unroll
    for (int j = 0; j < 2; j++) {
        float lo, hi; unpack2(acc2[j], lo, hi);
        g_c[((size_t)a * HN + hb + j) * BN + lane] = lo + hi + g_aconst[a * HN + hb + j];
    }
}

// =====================================================================
// K5a: partial attention logits over an h-QUARTER, 4 stations/thread,
// 128-thread blocks. smem 12KB, grid 1280 -> fills the regs-bound
// 6-blocks/SM cap in wave 1 (~24 warps/SM vs ~13 in R9).
// Partials (va[h]*tanh terms) add exactly across quarters; K5b sums 4.
// =====================================================================
__global__ void __launch_bounds__(128, 6) k5a_attn(
    const float* __restrict__ st, const float* __restrict__ dyn)
{
    constexpr int HQ = HN / 4;                      // 128 h per block
    int ab = blockIdx.x >> 2, hq = blockIdx.x & 3;
    int a = ab >> 5, b = ab & 31;
    __shared__ __align__(16) float sB[HQ * 24];     // 12KB: 12 splat-pairs per h
    int t = threadIdx.x;

    // staging: flat index -> coalesced LDG + conflict-free STS.64
    float2* s2 = reinterpret_cast<float2*>(sB);
    const float* arow = g_attp + ((size_t)a * HN + hq * HQ) * 12;
    int hbase = hq * HQ;
    for (int idx = t; idx < HQ * 12; idx += 128) {
        int hl = idx / 12, k = idx - hl * 12;
        float v = (k == 11) ? g_c[((size_t)a * HN + hbase + hl) * BN + b] : arow[idx];
        s2[idx] = make_float2(v, v);
    }

    // 4 stations per thread: pack A = (t, t+128), pack B = (t+256, t+384)
    int s0 = t, s1 = t + 128, s2i = t + 256, s3 = t + 384;
    unsigned long long uA[10], uB[10];
    const float* stb = st + (size_t)b * FSN * SN;
    uA[0] = pack2(stb[s0], stb[s1]);           uB[0] = pack2(stb[s2i], stb[s3]);
    uA[1] = pack2(stb[SN + s0], stb[SN + s1]); uB[1] = pack2(stb[SN + s2i], stb[SN + s3]);
    const float* dyb = dyn + (size_t)(a * BN + b) * FDN * SN;
    #pragma unroll
    for (int f = 0; f < 8; f++) {
        uA[2 + f] = pack2(dyb[f * SN + s0], dyb[f * SN + s1]);
        uB[2 + f] = pack2(dyb[f * SN + s2i], dyb[f * SN + s3]);
    }
    __syncthreads();

    unsigned long long laccA = 0, laccB = 0;
    #pragma unroll 2
    for (int h = 0; h < HQ; h++) {
        const ulonglong2* row = reinterpret_cast<const ulonglong2*>(sB + h * 24);
        ulonglong2 q0 = row[0], q1 = row[1], q2 = row[2];
        ulonglong2 q3 = row[3], q4 = row[4], q5 = row[5];
        unsigned long long caA = q5.y, cbA = 0ull;   // 4 independent chains
        unsigned long long caB = q5.y, cbB = 0ull;
        FFMA2(caA, q0.x, uA[0], caA); FFMA2(cbA, q0.y, uA[1], cbA);
        FFMA2(caB, q0.x, uB[0], caB); FFMA2(cbB, q0.y, uB[1], cbB);
        FFMA2(caA, q1.x, uA[2], caA); FFMA2(cbA, q1.y, uA[3], cbA);
        FFMA2(caB, q1.x, uB[2], caB); FFMA2(cbB, q1.y, uB[3], cbB);
        FFMA2(caA, q2.x, uA[4], caA); FFMA2(cbA, q2.y, uA[5], cbA);
        FFMA2(caB, q2.x, uB[4], caB); FFMA2(cbB, q2.y, uB[5], cbB);
        FFMA2(caA, q3.x, uA[6], caA); FFMA2(cbA, q3.y, uA[7], cbA);
        FFMA2(caB, q3.x, uB[6], caB); FFMA2(cbB, q3.y, uB[7], cbB);
        FFMA2(caA, q4.x, uA[8], caA); FFMA2(cbA, q4.y, uA[9], cbA);
        FFMA2(caB, q4.x, uB[8], caB); FFMA2(cbB, q4.y, uB[9], cbB);
        unsigned long long accA, accB;
        ADDX2(accA, caA, cbA);
        ADDX2(accB, caB, cbB);
        float a0, a1, a2, a3;
        unpack2(accA, a0, a1);
        unpack2(accB, a2, a3);
        unsigned long long tpA = pack2(tanh_fast(a0), tanh_fast(a1));
        unsigned long long tpB = pack2(tanh_fast(a2), tanh_fast(a3));
        FFMA2(laccA, q5.x, tpA, laccA);             // va pair
        FFMA2(laccB, q5.x, tpB, laccB);
    }
    float l0, l1, l2, l3;
    unpack2(laccA, l0, l1);
    unpack2(laccB, l2, l3);
    float* dst = g_lp + (size_t)hq * (AN * BN * SN) + (size_t)ab * SN;
    dst[s0]  = l0;
    dst[s1]  = l1;
    dst[s2i] = l2;
    dst[s3]  = l3;
}

// =====================================================================
// K5b: combine 4 partial logits, softmax over 512, st_w,
// d[h] = Pc.st_w + pconst. Grid = A*B (320), 256 threads. Light.
// =====================================================================
__global__ void __launch_bounds__(256) k5b_soft(const float* __restrict__ st)
{
    int ab = blockIdx.x;
    int a = ab >> 5, b = ab & 31;
    __shared__ float red[256];
    int t = threadIdx.x;

    constexpr size_t LQ = (size_t)AN * BN * SN;
    const float* lp = g_lp + (size_t)ab * SN;
    float l0 = lp[t]        + lp[LQ + t]        + lp[2 * LQ + t]        + lp[3 * LQ + t];
    float l1 = lp[t + 256]  + lp[LQ + t + 256]  + lp[2 * LQ + t + 256]  + lp[3 * LQ + t + 256];

    red[t] = fmaxf(l0, l1);
    __syncthreads();
    #pragma unroll
    for (int o = 128; o > 0; o >>= 1) {
        if (t < o) red[t] = fmaxf(red[t], red[t + o]);
        __syncthreads();
    }
    float m = red[0];
    __syncthreads();

    float e0 = __expf(l0 - m), e1 = __expf(l1 - m);
    red[t] = e0 + e1;
    __syncthreads();
    #pragma unroll
    for (int o = 128; o > 0; o >>= 1) {
        if (t < o) red[t] += red[t + o];
        __syncthreads();
    }
    float inv = __fdividef(1.0f, red[0]);
    __syncthreads();
    float at0 = e0 * inv, at1 = e1 * inv;

    const float* stb = st + (size_t)b * FSN * SN;
    float u00 = stb[t], u10 = stb[t + 256];
    float u01 = stb[SN + t], u11 = stb[SN + t + 256];

    red[t] = fmaf(at0, u00, at1 * u10);
    __syncthreads();
    #pragma unroll
    for (int o = 128; o > 0; o >>= 1) {
        if (t < o) red[t] += red[t + o];
        __syncthreads();
    }
    float stw0 = red[0];
    __syncthreads();

    red[t] = fmaf(at0, u01, at1 * u11);
    __syncthreads();
    #pragma unroll
    for (int o = 128; o > 0; o >>= 1) {
        if (t < o) red[t] += red[t + o];
        __syncthreads();
    }
    float stw1 = red[0];

    for (int h = t; h < HN; h += 256) {
        float pc0 = g_Pc[(a * HN + h) * 2 + 0];
        float pc1 = g_Pc[(a * HN + h) * 2 + 1];
        float pcn = g_ptrp[(size_t)(a * HN + h) * 4 + 2];
        g_d[(size_t)ab * HN + h] = fmaf(pc0, stw0, fmaf(pc1, stw1, pcn));
    }
}

// =====================================================================
// K5c: partial pointer probs over an h-HALF. Same occupancy mechanism
// as K5a: smem 16KB -> 8KB, grid 1280 -> 2560 (station-quarter x
// h-half) -> ~35 warps/SM (2x). Inner loop = R9-measured form (dual
// h-parity chains, accurate tanh). Partials summed by K5d.
// =====================================================================
__global__ void __launch_bounds__(64) k5c_ptr(const float* __restrict__ st)
{
    constexpr int HH = HN / 2;                    // 256 h per block
    int blk = blockIdx.x;
    int ab = blk >> 3;
    int q = (blk >> 1) & 3, hh = blk & 1;
    int a = ab >> 5, b = ab & 31;
    __shared__ __align__(16) float sP[HH * 8];    // 8KB: 4 splat-pairs per h
    int t = threadIdx.x;

    float2* s2 = reinterpret_cast<float2*>(sP);
    int hbase = hh * HH;
    const float* prow = g_ptrp + ((size_t)a * HN + hbase) * 4;
    for (int idx = t; idx < HH * 4; idx += 64) {
        int hl = idx >> 2, k = idx & 3;
        float v = (k == 2) ? g_d[(size_t)ab * HN + hbase + hl] : prow[idx];
        s2[idx] = make_float2(v, v);
    }

    int s0 = q * 128 + t, s1 = s0 + 64;
    const float* stb = st + (size_t)b * FSN * SN;
    unsigned long long up0 = pack2(stb[s0], stb[s1]);
    unsigned long long up1 = pack2(stb[SN + s0], stb[SN + s1]);
    __syncthreads();

    unsigned long long pacc0 = 0, pacc1 = 0;
    #pragma unroll 2
    for (int h = 0; h < HH; h += 2) {
        {
            const ulonglong2* row = reinterpret_cast<const ulonglong2*>(sP + h * 8);
            ulonglong2 q0 = row[0], q1 = row[1];   // {ps0,ps1}, {d,vp}
            unsigned long long acc = q1.x;
            FFMA2(acc, q0.x, up0, acc);
            FFMA2(acc, q0.y, up1, acc);
            float a0, a1; unpack2(acc, a0, a1);
            unsigned long long tp = pack2(tanh_acc(a0), tanh_acc(a1));
            FFMA2(pacc0, q1.y, tp, pacc0);
        }
        {
            const ulonglong2* row = reinterpret_cast<const ulonglong2*>(sP + (h + 1) * 8);
            ulonglong2 q0 = row[0], q1 = row[1];
            unsigned long long acc = q1.x;
            FFMA2(acc, q0.x, up0, acc);
            FFMA2(acc, q0.y, up1, acc);
            float a0, a1; unpack2(acc, a0, a1);
            unsigned long long tp = pack2(tanh_acc(a0), tanh_acc(a1));
            FFMA2(pacc1, q1.y, tp, pacc1);
        }
    }
    unsigned long long pacc; ADDX2(pacc, pacc0, pacc1);
    float p0, p1; unpack2(pacc, p0, p1);
    float* dst = g_pp + (size_t)hh * (AN * BN * SN) + (size_t)ab * SN;
    dst[s0] = p0;
    dst[s1] = p1;
}

// =====================================================================
// K5d: combine the 2 pointer partials into the output. Trivial.
// Grid = A*B*S/256 = 640, 256 threads.
// =====================================================================
__global__ void __launch_bounds__(256) k5d_comb(float* __restrict__ out_probs)
{
    constexpr size_t LQ = (size_t)AN * BN * SN;
    size_t idx = (size_t)blockIdx.x * 256 + threadIdx.x;
    out_probs[idx] = g_pp[idx] + g_pp[LQ + idx];
}

// =====================================================================
extern "C" void kernel_launch(void* const* d_in, const int* in_sizes, int n_in,
                              void* d_out, int out_size)
{
    const float* st   = (const float*)d_in[0];   // [B,FS,S]
    const float* dyn  = (const float*)d_in[1];   // [A,B,FD,S]
    const float* dec  = (const float*)d_in[2];   // [B,FS,1]
    const float* lhh  = (const float*)d_in[3];   // [B,H]
    const float* Ws   = (const float*)d_in[4];   // [H,FS]
    const float* bs   = (const float*)d_in[5];   // [H]
    const float* Wd   = (const float*)d_in[6];   // [A,H,FD]
    const float* bd   = (const float*)d_in[7];   // [A,H]
    const float* Wdec = (const float*)d_in[8];   // [A,H,FS]
    const float* bdec = (const float*)d_in[9];   // [A,H]
    const float* Wih  = (const float*)d_in[10];  // [A,3H,H]
    const float* Whh  = (const float*)d_in[11];  // [A,3H,H]
    const float* bih  = (const float*)d_in[12];  // [A,3H]
    const float* bhh  = (const float*)d_in[13];  // [A,3H]
    const float* va   = (const float*)d_in[14];  // [A,H]
    const float* Wa   = (const float*)d_in[15];  // [A,H,3H]
    const float* vp   = (const float*)d_in[16];  // [A,H]
    const float* Wp   = (const float*)d_in[17];  // [A,H,2H]

    float* out = (float*)d_out;
    float* out_probs = out;                         // [A,B,S]
    int have_hh = (out_size >= AN * BN * SN + AN * BN * HN);
    float* out_hh = out + (size_t)AN * BN * SN;     // [A,B,H]

    k12_pre_gh<<<K2_BLOCKS + K1_BLOCKS, 256>>>(
        Wa, Wp, Ws, Wd, bs, bd, va, vp, Wih, Wdec, bdec, bih, Whh, bhh, lhh);
    k3_gru<<<AN * BN * HN / 256, 256>>>(dec, lhh, out_hh, have_hh);
    k4_c<<<320, 256>>>(Wa);
    k5a_attn<<<AN * BN * 4, 128>>>(st, dyn);
    k5b_soft<<<AN * BN, 256>>>(st);
    k5c_ptr<<<AN * BN * 8, 64>>>(st);
    k5d_comb<<<AN * BN * SN / 256, 256>>>(out_probs);
}

// round 17
// speedup vs baseline: 1.1674x; 1.0801x over previous
#include <cuda_runtime.h>
#include <cstdint>

// Problem constants
constexpr int AN = 10;     // agents
constexpr int BN = 32;     // batch
constexpr int FSN = 2;     // static features
constexpr int FDN = 8;     // dynamic features
constexpr int HN = 512;    // hidden
constexpr int SN = 512;    // stations
constexpr int H3 = 3 * HN; // 1536
constexpr int H2 = 2 * HN; // 1024

// ---------------- scratch (no allocations allowed) ----------------
__device__ float g_attp[AN * HN * 12];   // {ms0,ms1,md0..7,va,0} per (a,h)
__device__ float g_ptrp[AN * HN * 4];    // {ps0,ps1,pconst,vp} per (a,h)
__device__ float g_Pc[AN * HN * 2];      // Wp_c @ Ws
__device__ float g_aconst[AN * HN];      // Wa_s@bs + Wa_d@bd
__device__ float g_G[AN * H3 * 2];       // Wih @ Wdec  (rank-2 GRU input)
__device__ float g_gib[AN * H3];         // Wih @ bdec + bih
__device__ float g_gh[AN * H3 * BN];     // Whh @ last_hh^T + bhh, [a][j3][b]
__device__ float g_hnew[AN * BN * HN];   // new hidden, [a][b][h]
__device__ float g_c[AN * HN * BN];      // Wa_h@h_new + aconst, [a][h][b]
__device__ float g_lp[4 * AN * BN * SN]; // partial attention logits, 4 h-quarters
__device__ float g_d[AN * BN * HN];      // pointer per-h additive term, [ab][h]
__device__ float g_pp[2 * AN * BN * SN]; // partial pointer probs, 2 h-halves

// ---------------- packed f32x2 helpers ----------------
#define FFMA2(d, a, b, c) \
    asm("fma.rn.f32x2 %0, %1, %2, %3;" : "=l"(d) : "l"(a), "l"(b), "l"(c))
#define ADDX2(d, a, b) \
    asm("add.rn.f32x2 %0, %1, %2;" : "=l"(d) : "l"(a), "l"(b))

__device__ __forceinline__ unsigned long long pack2(float lo, float hi) {
    unsigned long long r;
    asm("mov.b64 %0, {%1, %2};" : "=l"(r) : "f"(lo), "f"(hi));
    return r;
}
__device__ __forceinline__ void unpack2(unsigned long long v, float& lo, float& hi) {
    asm("mov.b64 {%0, %1}, %2;" : "=f"(lo), "=f"(hi) : "l"(v));
}

// ---------------- math helpers ----------------
// accurate tanh (~1e-7 abs): 2 MUFU + ~4 FMA-pipe ops, branch-free.
__device__ __forceinline__ float tanh_acc(float x) {
    float e = __expf(2.0f * x);
    return 1.0f - __fdividef(2.0f, e + 1.0f);
}
// fast tanh: 1 MUFU (MUFU.TANH), max abs err ~5e-4 (PTX: 2^-10.99),
// RMS ~1.5e-4. Error budget for the pointer output: sqrt(512)*0.0625*
// 1.5e-4 ~ 2e-4 abs vs output scale ~0.85 -> rel ~2.5e-4, 4x under gate.
__device__ __forceinline__ float tanh_fast(float x) {
    float y;
    asm("tanh.approx.f32 %0, %1;" : "=f"(y) : "f"(x));
    return y;
}
__device__ __forceinline__ float sigmoid_acc(float x) {
    return __fdividef(1.0f, 1.0f + __expf(-x));
}

// =====================================================================
// K12: fused K1 (low-rank precompute, HBM-bound) + K2 (Whh GEMM,
// FMA-bound). Independent work; one launch so the two bottlenecks
// overlap on different pipes instead of serializing.
// =====================================================================
constexpr int K2_BLOCKS = 240;   // A * (H3/64)
constexpr int K1_BLOCKS = 2560;  // (A*H + A*3H) warps / 8

__global__ void __launch_bounds__(256) k12_pre_gh(
    const float* __restrict__ Wa, const float* __restrict__ Wp,
    const float* __restrict__ Ws, const float* __restrict__ Wd,
    const float* __restrict__ bs, const float* __restrict__ bd,
    const float* __restrict__ va, const float* __restrict__ vp,
    const float* __restrict__ Wih, const float* __restrict__ Wdec,
    const float* __restrict__ bdec, const float* __restrict__ bih,
    const float* __restrict__ Whh, const float* __restrict__ bhh,
    const float* __restrict__ lhh)
{
    __shared__ float sh[BN * 258];          // used by the K2 path only
    int lane = threadIdx.x & 31;

    if (blockIdx.x < K2_BLOCKS) {
        // ---------------- K2 body: gh = Whh @ last_hh^T + bhh ----------------
        int a = blockIdx.x / 24;
        int jblk = (blockIdx.x % 24) * 64;
        int wid = threadIdx.x >> 5;
        int j3b = jblk + wid * 8;

        unsigned long long acc2[8];
        #pragma unroll
        for (int j = 0; j < 8; j++) acc2[j] = 0ull;

        for (int kc = 0; kc < 2; kc++) {
            if (kc) __syncthreads();
            for (int i = threadIdx.x; i < BN * 256; i += 256) {
                int b = i >> 8, k = i & 255;
                sh[b * 258 + k] = lhh[b * HN + kc * 256 + k];
            }
            __syncthreads();
            const float* w0 = Whh + (size_t)(a * H3 + j3b) * HN + kc * 256;
            #pragma unroll 2
            for (int k4 = 0; k4 < 256; k4 += 4) {
                unsigned long long h2a =
                    *reinterpret_cast<const unsigned long long*>(&sh[lane * 258 + k4]);
                unsigned long long h2b =
                    *reinterpret_cast<const unsigned long long*>(&sh[lane * 258 + k4 + 2]);
                #pragma unroll
                for (int j = 0; j < 8; j++) {
                    ulonglong2 wv = *reinterpret_cast<const ulonglong2*>(w0 + (size_t)j * HN + k4);
                    FFMA2(acc2[j], wv.x, h2a, acc2[j]);
                    FFMA2(acc2[j], wv.y, h2b, acc2[j]);
                }
            }
        }
        #pragma unroll
        for (int j = 0; j < 8; j++) {
            float lo, hi; unpack2(acc2[j], lo, hi);
            g_gh[((size_t)a * H3 + j3b + j) * BN + lane] = lo + hi + bhh[a * H3 + j3b + j];
        }
        return;
    }

    // ---------------- K1 body: one warp per output row ----------------
    int wg = ((blockIdx.x - K2_BLOCKS) * blockDim.x + threadIdx.x) >> 5;

    if (wg < AN * HN) {
        int a = wg / HN, h = wg % HN;
        const float* war = Wa + (size_t)(a * HN + h) * H3;
        const float* wpr = Wp + (size_t)(a * HN + h) * H2;
        float acc[16];
        #pragma unroll
        for (int i = 0; i < 16; i++) acc[i] = 0.0f;

        for (int j = lane; j < HN; j += 32) {
            float was = war[j];
            float wad = war[HN + j];
            float wps = wpr[j];
            float wpc = wpr[HN + j];
            float ws0 = Ws[j * 2 + 0], ws1 = Ws[j * 2 + 1];
            acc[0] = fmaf(was, ws0, acc[0]);
            acc[1] = fmaf(was, ws1, acc[1]);
            const float* wdj = Wd + (size_t)(a * HN + j) * FDN;
            #pragma unroll
            for (int f = 0; f < 8; f++) acc[2 + f] = fmaf(wad, wdj[f], acc[2 + f]);
            acc[10] = fmaf(was, bs[j], fmaf(wad, bd[a * HN + j], acc[10]));
            acc[11] = fmaf(wps, ws0, acc[11]);
            acc[12] = fmaf(wps, ws1, acc[12]);
            acc[13] = fmaf(wpc, ws0, acc[13]);
            acc[14] = fmaf(wpc, ws1, acc[14]);
            acc[15] = fmaf(wps + wpc, bs[j], acc[15]);
        }
        #pragma unroll
        for (int i = 0; i < 16; i++) {
            #pragma unroll
            for (int off = 16; off > 0; off >>= 1)
                acc[i] += __shfl_down_sync(0xffffffffu, acc[i], off);
        }
        if (lane == 0) {
            float* ap = g_attp + (size_t)(a * HN + h) * 12;
            ap[0] = acc[0]; ap[1] = acc[1];
            #pragma unroll
            for (int f = 0; f < 8; f++) ap[2 + f] = acc[2 + f];
            ap[10] = va[a * HN + h];
            ap[11] = 0.0f;
            g_aconst[a * HN + h] = acc[10];
            float* pp = g_ptrp + (size_t)(a * HN + h) * 4;
            pp[0] = acc[11]; pp[1] = acc[12]; pp[2] = acc[15]; pp[3] = vp[a * HN + h];
            g_Pc[(a * HN + h) * 2 + 0] = acc[13];
            g_Pc[(a * HN + h) * 2 + 1] = acc[14];
        }
    } else if (wg < AN * HN + AN * H3) {
        int idx = wg - AN * HN;
        int a = idx / H3, j3 = idx % H3;
        const float* wr = Wih + (size_t)(a * H3 + j3) * HN;
        float g0 = 0.0f, g1 = 0.0f, gb = 0.0f;
        for (int k = lane; k < HN; k += 32) {
            float w = wr[k];
            g0 = fmaf(w, Wdec[(a * HN + k) * 2 + 0], g0);
            g1 = fmaf(w, Wdec[(a * HN + k) * 2 + 1], g1);
            gb = fmaf(w, bdec[a * HN + k], gb);
        }
        #pragma unroll
        for (int off = 16; off > 0; off >>= 1) {
            g0 += __shfl_down_sync(0xffffffffu, g0, off);
            g1 += __shfl_down_sync(0xffffffffu, g1, off);
            gb += __shfl_down_sync(0xffffffffu, gb, off);
        }
        if (lane == 0) {
            g_G[(size_t)(a * H3 + j3) * 2 + 0] = g0;
            g_G[(size_t)(a * H3 + j3) * 2 + 1] = g1;
            g_gib[a * H3 + j3] = gb + bih[a * H3 + j3];
        }
    }
}

// =====================================================================
// K3: GRU elementwise (gi collapsed to rank-2), write h_new (+ hh output)
// Accurate tanh kept: feeds the hh output directly.
// =====================================================================
__global__ void __launch_bounds__(256) k3_gru(
    const float* __restrict__ dec, const float* __restrict__ lhh,
    float* __restrict__ out_hh, int write_out)
{
    int idx = blockIdx.x * blockDim.x + threadIdx.x;
    int h = idx % HN;
    int b = (idx / HN) % BN;
    int a = idx / (BN * HN);

    float d0 = dec[b * 2 + 0], d1 = dec[b * 2 + 1];

    int jr = h, jz = HN + h, jn = 2 * HN + h;
    const float* Gb = g_G + (size_t)a * H3 * 2;
    const float* gib = g_gib + (size_t)a * H3;
    float ir = fmaf(Gb[jr * 2], d0, fmaf(Gb[jr * 2 + 1], d1, gib[jr]));
    float iz = fmaf(Gb[jz * 2], d0, fmaf(Gb[jz * 2 + 1], d1, gib[jz]));
    float in_ = fmaf(Gb[jn * 2], d0, fmaf(Gb[jn * 2 + 1], d1, gib[jn]));

    const float* ghb = g_gh + (size_t)a * H3 * BN;
    float hr = ghb[(size_t)jr * BN + b];
    float hz = ghb[(size_t)jz * BN + b];
    float hn = ghb[(size_t)jn * BN + b];

    float r = sigmoid_acc(ir + hr);
    float z = sigmoid_acc(iz + hz);
    float n = tanh_acc(in_ + r * hn);
    float hprev = lhh[b * HN + h];
    float hnew = fmaf(1.0f - z, n, z * hprev);

    g_hnew[((size_t)a * BN + b) * HN + h] = hnew;
    if (write_out) out_hh[((size_t)a * BN + b) * HN + h] = hnew;
}

// =====================================================================
// K4: c[a][h][b] = sum_j Wa[a][h][2H+j] * h_new[a][b][j] + aconst[a][h]
// Packed-k structure; 2 rows/warp, 16 rows/block. Grid = 320.
// =====================================================================
__global__ void __launch_bounds__(256) k4_c(const float* __restrict__ Wa)
{
    __shared__ float sh[BN * 258];
    int a = blockIdx.x / 32;
    int hblk = (blockIdx.x % 32) * 16;
    int wid = threadIdx.x >> 5, lane = threadIdx.x & 31;
    int hb = hblk + wid * 2;

    unsigned long long acc2[2];
    #pragma unroll
    for (int j = 0; j < 2; j++) acc2[j] = 0ull;

    for (int kc = 0; kc < 2; kc++) {
        if (kc) __syncthreads();
        for (int i = threadIdx.x; i < BN * 256; i += 256) {
            int b = i >> 8, k = i & 255;
            sh[b * 258 + k] = g_hnew[((size_t)a * BN + b) * HN + kc * 256 + k];
        }
        __syncthreads();
        const float* w0 = Wa + (size_t)(a * HN + hb) * H3 + 2 * HN + kc * 256;
        #pragma unroll 2
        for (int k4 = 0; k4 < 256; k4 += 4) {
            unsigned long long h2a =
                *reinterpret_cast<const unsigned long long*>(&sh[lane * 258 + k4]);
            unsigned long long h2b =
                *reinterpret_cast<const unsigned long long*>(&sh[lane * 258 + k4 + 2]);
            #pragma unroll
            for (int j = 0; j < 2; j++) {
                ulonglong2 wv = *reinterpret_cast<const ulonglong2*>(w0 + (size_t)j * H3 + k4);
                FFMA2(acc2[j], wv.x, h2a, acc2[j]);
                FFMA2(acc2[j], wv.y, h2b, acc2[j]);
            }
        }
    }
    #pragma unroll
    for (int j = 0; j < 2; j++) {
        float lo, hi; unpack2(acc2[j], lo, hi);
        g_c[((size_t)a * HN + hb + j) * BN + lane] = lo + hi + g_aconst[a * HN + hb + j];
    }
}

// =====================================================================
// K5a: partial attention logits over an h-QUARTER, 4 stations/thread,
// 128-thread blocks. smem 12KB, grid 1280 (measured R16: 55.8us,
// occ 29.6%, fma 45%). Frozen this round.
// =====================================================================
__global__ void __launch_bounds__(128, 6) k5a_attn(
    const float* __restrict__ st, const float* __restrict__ dyn)
{
    constexpr int HQ = HN / 4;                      // 128 h per block
    int ab = blockIdx.x >> 2, hq = blockIdx.x & 3;
    int a = ab >> 5, b = ab & 31;
    __shared__ __align__(16) float sB[HQ * 24];     // 12KB: 12 splat-pairs per h
    int t = threadIdx.x;

    // staging: flat index -> coalesced LDG + conflict-free STS.64
    float2* s2 = reinterpret_cast<float2*>(sB);
    const float* arow = g_attp + ((size_t)a * HN + hq * HQ) * 12;
    int hbase = hq * HQ;
    for (int idx = t; idx < HQ * 12; idx += 128) {
        int hl = idx / 12, k = idx - hl * 12;
        float v = (k == 11) ? g_c[((size_t)a * HN + hbase + hl) * BN + b] : arow[idx];
        s2[idx] = make_float2(v, v);
    }

    // 4 stations per thread: pack A = (t, t+128), pack B = (t+256, t+384)
    int s0 = t, s1 = t + 128, s2i = t + 256, s3 = t + 384;
    unsigned long long uA[10], uB[10];
    const float* stb = st + (size_t)b * FSN * SN;
    uA[0] = pack2(stb[s0], stb[s1]);           uB[0] = pack2(stb[s2i], stb[s3]);
    uA[1] = pack2(stb[SN + s0], stb[SN + s1]); uB[1] = pack2(stb[SN + s2i], stb[SN + s3]);
    const float* dyb = dyn + (size_t)(a * BN + b) * FDN * SN;
    #pragma unroll
    for (int f = 0; f < 8; f++) {
        uA[2 + f] = pack2(dyb[f * SN + s0], dyb[f * SN + s1]);
        uB[2 + f] = pack2(dyb[f * SN + s2i], dyb[f * SN + s3]);
    }
    __syncthreads();

    unsigned long long laccA = 0, laccB = 0;
    #pragma unroll 2
    for (int h = 0; h < HQ; h++) {
        const ulonglong2* row = reinterpret_cast<const ulonglong2*>(sB + h * 24);
        ulonglong2 q0 = row[0], q1 = row[1], q2 = row[2];
        ulonglong2 q3 = row[3], q4 = row[4], q5 = row[5];
        unsigned long long caA = q5.y, cbA = 0ull;   // 4 independent chains
        unsigned long long caB = q5.y, cbB = 0ull;
        FFMA2(caA, q0.x, uA[0], caA); FFMA2(cbA, q0.y, uA[1], cbA);
        FFMA2(caB, q0.x, uB[0], caB); FFMA2(cbB, q0.y, uB[1], cbB);
        FFMA2(caA, q1.x, uA[2], caA); FFMA2(cbA, q1.y, uA[3], cbA);
        FFMA2(caB, q1.x, uB[2], caB); FFMA2(cbB, q1.y, uB[3], cbB);
        FFMA2(caA, q2.x, uA[4], caA); FFMA2(cbA, q2.y, uA[5], cbA);
        FFMA2(caB, q2.x, uB[4], caB); FFMA2(cbB, q2.y, uB[5], cbB);
        FFMA2(caA, q3.x, uA[6], caA); FFMA2(cbA, q3.y, uA[7], cbA);
        FFMA2(caB, q3.x, uB[6], caB); FFMA2(cbB, q3.y, uB[7], cbB);
        FFMA2(caA, q4.x, uA[8], caA); FFMA2(cbA, q4.y, uA[9], cbA);
        FFMA2(caB, q4.x, uB[8], caB); FFMA2(cbB, q4.y, uB[9], cbB);
        unsigned long long accA, accB;
        ADDX2(accA, caA, cbA);
        ADDX2(accB, caB, cbB);
        float a0, a1, a2, a3;
        unpack2(accA, a0, a1);
        unpack2(accB, a2, a3);
        unsigned long long tpA = pack2(tanh_fast(a0), tanh_fast(a1));
        unsigned long long tpB = pack2(tanh_fast(a2), tanh_fast(a3));
        FFMA2(laccA, q5.x, tpA, laccA);             // va pair
        FFMA2(laccB, q5.x, tpB, laccB);
    }
    float l0, l1, l2, l3;
    unpack2(laccA, l0, l1);
    unpack2(laccB, l2, l3);
    float* dst = g_lp + (size_t)hq * (AN * BN * SN) + (size_t)ab * SN;
    dst[s0]  = l0;
    dst[s1]  = l1;
    dst[s2i] = l2;
    dst[s3]  = l3;
}

// =====================================================================
// K5b: combine 4 partial logits, softmax over 512, st_w,
// d[h] = Pc.st_w + pconst. Grid = A*B (320), 256 threads. Light.
// =====================================================================
__global__ void __launch_bounds__(256) k5b_soft(const float* __restrict__ st)
{
    int ab = blockIdx.x;
    int a = ab >> 5, b = ab & 31;
    __shared__ float red[256];
    int t = threadIdx.x;

    constexpr size_t LQ = (size_t)AN * BN * SN;
    const float* lp = g_lp + (size_t)ab * SN;
    float l0 = lp[t]        + lp[LQ + t]        + lp[2 * LQ + t]        + lp[3 * LQ + t];
    float l1 = lp[t + 256]  + lp[LQ + t + 256]  + lp[2 * LQ + t + 256]  + lp[3 * LQ + t + 256];

    red[t] = fmaxf(l0, l1);
    __syncthreads();
    #pragma unroll
    for (int o = 128; o > 0; o >>= 1) {
        if (t < o) red[t] = fmaxf(red[t], red[t + o]);
        __syncthreads();
    }
    float m = red[0];
    __syncthreads();

    float e0 = __expf(l0 - m), e1 = __expf(l1 - m);
    red[t] = e0 + e1;
    __syncthreads();
    #pragma unroll
    for (int o = 128; o > 0; o >>= 1) {
        if (t < o) red[t] += red[t + o];
        __syncthreads();
    }
    float inv = __fdividef(1.0f, red[0]);
    __syncthreads();
    float at0 = e0 * inv, at1 = e1 * inv;

    const float* stb = st + (size_t)b * FSN * SN;
    float u00 = stb[t], u10 = stb[t + 256];
    float u01 = stb[SN + t], u11 = stb[SN + t + 256];

    red[t] = fmaf(at0, u00, at1 * u10);
    __syncthreads();
    #pragma unroll
    for (int o = 128; o > 0; o >>= 1) {
        if (t < o) red[t] += red[t + o];
        __syncthreads();
    }
    float stw0 = red[0];
    __syncthreads();

    red[t] = fmaf(at0, u01, at1 * u11);
    __syncthreads();
    #pragma unroll
    for (int o = 128; o > 0; o >>= 1) {
        if (t < o) red[t] += red[t + o];
        __syncthreads();
    }
    float stw1 = red[0];

    for (int h = t; h < HN; h += 256) {
        float pc0 = g_Pc[(a * HN + h) * 2 + 0];
        float pc1 = g_Pc[(a * HN + h) * 2 + 1];
        float pcn = g_ptrp[(size_t)(a * HN + h) * 4 + 2];
        g_d[(size_t)ab * HN + h] = fmaf(pc0, stw0, fmaf(pc1, stw1, pcn));
    }
}

// =====================================================================
// K5c: partial pointer probs over an h-HALF. THE dominant kernel by
// the corrected budget (84M tanhs): accurate tanh = 2 MUFU each ->
// ~40us MUFU floor, ~80-100us at observed ~50% saturation. Switch to
// tanh_fast (1 MUFU, RMS err 1.5e-4): output error est. ~2.5e-4 rel,
// 4x under the 1e-3 gate. MUFU/iter 8->4, FMA/iter ~20->8.
// =====================================================================
__global__ void __launch_bounds__(64) k5c_ptr(const float* __restrict__ st)
{
    constexpr int HH = HN / 2;                    // 256 h per block
    int blk = blockIdx.x;
    int ab = blk >> 3;
    int q = (blk >> 1) & 3, hh = blk & 1;
    int a = ab >> 5, b = ab & 31;
    __shared__ __align__(16) float sP[HH * 8];    // 8KB: 4 splat-pairs per h
    int t = threadIdx.x;

    float2* s2 = reinterpret_cast<float2*>(sP);
    int hbase = hh * HH;
    const float* prow = g_ptrp + ((size_t)a * HN + hbase) * 4;
    for (int idx = t; idx < HH * 4; idx += 64) {
        int hl = idx >> 2, k = idx & 3;
        float v = (k == 2) ? g_d[(size_t)ab * HN + hbase + hl] : prow[idx];
        s2[idx] = make_float2(v, v);
    }

    int s0 = q * 128 + t, s1 = s0 + 64;
    const float* stb = st + (size_t)b * FSN * SN;
    unsigned long long up0 = pack2(stb[s0], stb[s1]);
    unsigned long long up1 = pack2(stb[SN + s0], stb[SN + s1]);
    __syncthreads();

    unsigned long long pacc0 = 0, pacc1 = 0;
    #pragma unroll 2
    for (int h = 0; h < HH; h += 2) {
        {
            const ulonglong2* row = reinterpret_cast<const ulonglong2*>(sP + h * 8);
            ulonglong2 q0 = row[0], q1 = row[1];   // {ps0,ps1}, {d,vp}
            unsigned long long acc = q1.x;
            FFMA2(acc, q0.x, up0, acc);
            FFMA2(acc, q0.y, up1, acc);
            float a0, a1; unpack2(acc, a0, a1);
            unsigned long long tp = pack2(tanh_fast(a0), tanh_fast(a1));
            FFMA2(pacc0, q1.y, tp, pacc0);
        }
        {
            const ulonglong2* row = reinterpret_cast<const ulonglong2*>(sP + (h + 1) * 8);
            ulonglong2 q0 = row[0], q1 = row[1];
            unsigned long long acc = q1.x;
            FFMA2(acc, q0.x, up0, acc);
            FFMA2(acc, q0.y, up1, acc);
            float a0, a1; unpack2(acc, a0, a1);
            unsigned long long tp = pack2(tanh_fast(a0), tanh_fast(a1));
            FFMA2(pacc1, q1.y, tp, pacc1);
        }
    }
    unsigned long long pacc; ADDX2(pacc, pacc0, pacc1);
    float p0, p1; unpack2(pacc, p0, p1);
    float* dst = g_pp + (size_t)hh * (AN * BN * SN) + (size_t)ab * SN;
    dst[s0] = p0;
    dst[s1] = p1;
}

// =====================================================================
// K5d: combine the 2 pointer partials into the output. Trivial.
// Grid = A*B*S/256 = 640, 256 threads.
// =====================================================================
__global__ void __launch_bounds__(256) k5d_comb(float* __restrict__ out_probs)
{
    constexpr size_t LQ = (size_t)AN * BN * SN;
    size_t idx = (size_t)blockIdx.x * 256 + threadIdx.x;
    out_probs[idx] = g_pp[idx] + g_pp[LQ + idx];
}

// =====================================================================
extern "C" void kernel_launch(void* const* d_in, const int* in_sizes, int n_in,
                              void* d_out, int out_size)
{
    const float* st   = (const float*)d_in[0];   // [B,FS,S]
    const float* dyn  = (const float*)d_in[1];   // [A,B,FD,S]
    const float* dec  = (const float*)d_in[2];   // [B,FS,1]
    const float* lhh  = (const float*)d_in[3];   // [B,H]
    const float* Ws   = (const float*)d_in[4];   // [H,FS]
    const float* bs   = (const float*)d_in[5];   // [H]
    const float* Wd   = (const float*)d_in[6];   // [A,H,FD]
    const float* bd   = (const float*)d_in[7];   // [A,H]
    const float* Wdec = (const float*)d_in[8];   // [A,H,FS]
    const float* bdec = (const float*)d_in[9];   // [A,H]
    const float* Wih  = (const float*)d_in[10];  // [A,3H,H]
    const float* Whh  = (const float*)d_in[11];  // [A,3H,H]
    const float* bih  = (const float*)d_in[12];  // [A,3H]
    const float* bhh  = (const float*)d_in[13];  // [A,3H]
    const float* va   = (const float*)d_in[14];  // [A,H]
    const float* Wa   = (const float*)d_in[15];  // [A,H,3H]
    const float* vp   = (const float*)d_in[16];  // [A,H]
    const float* Wp   = (const float*)d_in[17];  // [A,H,2H]

    float* out = (float*)d_out;
    float* out_probs = out;                         // [A,B,S]
    int have_hh = (out_size >= AN * BN * SN + AN * BN * HN);
    float* out_hh = out + (size_t)AN * BN * SN;     // [A,B,H]

    k12_pre_gh<<<K2_BLOCKS + K1_BLOCKS, 256>>>(
        Wa, Wp, Ws, Wd, bs, bd, va, vp, Wih, Wdec, bdec, bih, Whh, bhh, lhh);
    k3_gru<<<AN * BN * HN / 256, 256>>>(dec, lhh, out_hh, have_hh);
    k4_c<<<320, 256>>>(Wa);
    k5a_attn<<<AN * BN * 4, 128>>>(st, dyn);
    k5b_soft<<<AN * BN, 256>>>(st);
    k5c_ptr<<<AN * BN * 8, 64>>>(st);
    k5d_comb<<<AN * BN * SN / 256, 256>>>(out_probs);
}